// round 11
// baseline (speedup 1.0000x reference)
#include <cuda_runtime.h>

#define A_ANG 192
#define DDET  576
#define W_IMG 384
#define PADW  672
#define POFF  24
#define CMAGIC 12582912.0f            /* 2^23 + 2^22 */
#define CBITS  0x4B400000             /* __float_as_int(CMAGIC) */

// Scratch (__device__ globals: allocation-free). g_pad is zero-initialized at
// module load; padding slots are never written, so they stay zero across all
// graph replays (out-of-range detector taps contribute exactly 0).
// Gather base indices i0 span [-21, 594]; slots 3..619 of 672 are addressable.
__device__ float2 g_pad[A_ANG * PADW];     // 1.0 MB packed (sino, pred) table
__device__ float  g_img[W_IMG * W_IMG];    // backprojection of raw sino

// ---------------------------------------------------------------------------
// Kernel 1: composite conv (uniform 9x9 path, no divergence).
// Builds its own tables in smem, overlapped with the tile global loads:
//   sG[d][e] = sum_c w2[c,d]*w1[c,e]   (all threads, ~3 entries each)
//   sW9[a][b] = sum_{d+e=(a,b)} sG     (81 threads)
//   sB[d] = sum_c w2[c,d]*b1[c]        (25 threads)  bias = b2 + sum sB
// Border pixels get (wrong) 9x9-on-zero-padded values; border_fix_kernel
// recomputes them exactly afterward.
// ---------------------------------------------------------------------------
#define CTX 32
#define CTY 8
__global__ void __launch_bounds__(CTX * CTY) conv12_kernel(
    const float* __restrict__ sino,
    const float* __restrict__ w1, const float* __restrict__ b1,
    const float* __restrict__ w2, const float* __restrict__ b2,
    float* __restrict__ sino_pred)
{
    __shared__ float t[CTY + 8][CTX + 8];   // 16 x 40, halo 4, zero-padded
    __shared__ float sG[625];
    __shared__ float sB[25];
    __shared__ float sW[81];
    __shared__ float sbias;

    const int tid = threadIdx.y * CTX + threadIdx.x;
    const int bx0 = blockIdx.x * CTX, by0 = blockIdx.y * CTY;

    // tile load first (long-latency globals in flight)
    for (int i = tid; i < (CTY + 8) * (CTX + 8); i += CTX * CTY) {
        int ly = i / (CTX + 8), lx = i % (CTX + 8);
        int gy = by0 - 4 + ly, gx = bx0 - 4 + lx;
        float v = 0.0f;
        if ((unsigned)gy < A_ANG && (unsigned)gx < DDET) v = sino[gy * DDET + gx];
        t[ly][lx] = v;
    }
    // table build overlaps the tile-load latency
    for (int i = tid; i < 625; i += CTX * CTY) {
        int d = i / 25, e = i % 25;
        float g = 0.0f;
        #pragma unroll
        for (int c = 0; c < 16; c++)
            g = fmaf(__ldg(&w2[c * 25 + d]), __ldg(&w1[c * 25 + e]), g);
        sG[i] = g;
    }
    if (tid < 25) {
        float s = 0.0f;
        #pragma unroll
        for (int c = 0; c < 16; c++) s = fmaf(__ldg(&w2[c * 25 + tid]), __ldg(&b1[c]), s);
        sB[tid] = s;
    }
    __syncthreads();
    if (tid < 81) {
        int tty = tid / 9, ttx = tid % 9;
        float w = 0.0f;
        for (int dy = 0; dy < 5; dy++) {
            int ey = tty - dy; if (ey < 0 || ey > 4) continue;
            for (int dx = 0; dx < 5; dx++) {
                int ex = ttx - dx; if (ex < 0 || ex > 4) continue;
                w += sG[(dy * 5 + dx) * 25 + ey * 5 + ex];
            }
        }
        sW[tid] = w;
    }
    if (tid == 96) {
        float bias = b2[0];
        #pragma unroll
        for (int d = 0; d < 25; d++) bias += sB[d];
        sbias = bias;
    }
    __syncthreads();

    const int tx = threadIdx.x, ty = threadIdx.y;
    const int gx = bx0 + tx, gy = by0 + ty;
    float acc = sbias;
    #pragma unroll
    for (int a = 0; a < 9; a++)
        #pragma unroll
        for (int b = 0; b < 9; b++)
            acc = fmaf(t[ty + a][tx + b], sW[a * 9 + b], acc);

    sino_pred[gy * DDET + gx] = acc;
    g_pad[gy * PADW + POFF + gx] = make_float2(t[ty + 4][tx + 4], acc);
}

// ---------------------------------------------------------------------------
// Kernel 1b: exact recompute for exactly the 3056 border pixels.
// 12 blocks x 256 threads; each block builds sG/sB itself.
// n < 1152: rows 0,1 | n < 2304: rows 190,191 | else: cols {0,1,574,575}.
// ---------------------------------------------------------------------------
__global__ void __launch_bounds__(256) border_fix_kernel(
    const float* __restrict__ sino,
    const float* __restrict__ w1, const float* __restrict__ b1,
    const float* __restrict__ w2, const float* __restrict__ b2,
    float* __restrict__ sino_pred)
{
    __shared__ float sG[625];
    __shared__ float sB[25];
    const int tid = threadIdx.x;

    for (int i = tid; i < 625; i += 256) {
        int d = i / 25, e = i % 25;
        float g = 0.0f;
        #pragma unroll
        for (int c = 0; c < 16; c++)
            g = fmaf(__ldg(&w2[c * 25 + d]), __ldg(&w1[c * 25 + e]), g);
        sG[i] = g;
    }
    if (tid < 25) {
        float s = 0.0f;
        #pragma unroll
        for (int c = 0; c < 16; c++) s = fmaf(__ldg(&w2[c * 25 + tid]), __ldg(&b1[c]), s);
        sB[tid] = s;
    }
    __syncthreads();

    const int n = blockIdx.x * 256 + tid;
    if (n >= 3056) return;
    int gy, gx;
    if (n < 1152)      { gy = n / DDET;               gx = n % DDET; }
    else if (n < 2304) { gy = 190 + (n - 1152) / DDET; gx = (n - 1152) % DDET; }
    else {
        int m = n - 2304;
        gy = 2 + m / 4;
        int j = m % 4;
        gx = (j < 2) ? j : 572 + j;
    }

    float acc = b2[0];
    for (int dy = 0; dy < 5; dy++) {
        int hy = gy + dy - 2; if ((unsigned)hy >= A_ANG) continue;
        for (int dx = 0; dx < 5; dx++) {
            int hx = gx + dx - 2; if ((unsigned)hx >= DDET) continue;
            float a2 = sB[dy * 5 + dx];
            #pragma unroll
            for (int ey = 0; ey < 5; ey++) {
                int sy = hy + ey - 2; if ((unsigned)sy >= A_ANG) continue;
                #pragma unroll
                for (int ex = 0; ex < 5; ex++) {
                    int sx = hx + ex - 2; if ((unsigned)sx >= DDET) continue;
                    a2 = fmaf(__ldg(&sino[sy * DDET + sx]),
                              sG[(dy * 5 + dx) * 25 + ey * 5 + ex], a2);
                }
            }
            acc += a2;
        }
    }
    const int p = gy * DDET + gx;
    sino_pred[p] = acc;
    g_pad[gy * PADW + POFF + gx] = make_float2(__ldg(&sino[p]), acc);
}

// ---------------------------------------------------------------------------
// Kernel 2: dual fan-beam backprojection.
// 32x32 tile / 1024 threads (144 blocks ~ 1/SM), 2-angle unroll.
// Floor via 2^23 trick on (s - 0.5): all fma/alu-pipe ops on the address
// chain (no F2I/I2F cross-pipe latency). At exact-integer s either rounding
// yields the identical interpolated value, so this is exact.
// ---------------------------------------------------------------------------
__global__ void __launch_bounds__(1024) backproj_kernel(
    const float* __restrict__ angles,
    float* __restrict__ img_sino)
{
    __shared__ float2 s_ang[A_ANG];
    const int tid = threadIdx.x;
    if (tid < A_ANG) {
        float sv, cv;
        sincosf(angles[tid], &sv, &cv);
        s_ang[tid] = make_float2(cv, sv);
    }
    __syncthreads();

    // warp footprint 8x4; warps tiled 4 across x, 8 down y
    const int lane = tid & 31, wid = tid >> 5;
    const int lx = lane & 7,  ly = lane >> 3;      // 8 x 4
    const int wx = wid & 3,   wy = wid >> 2;       // 4 x 8
    const int x = blockIdx.x * 32 + wx * 8 + lx;
    const int y = blockIdx.y * 32 + wy * 4 + ly;
    const float X = (float)x - 191.5f;
    const float Y = (float)y - 191.5f;

    float accA = 0.f, accB = 0.f;
    for (int a = 0; a < A_ANG; a += 2) {
        float2 v0[2], v1[2];
        float fr[2];
        #pragma unroll
        for (int j = 0; j < 2; j++) {
            const float2 cs = s_ang[a + j];
            const float px = fmaf(cs.x, X, cs.y * Y);
            const float py = fmaf(-cs.y, X, cs.x * Y);
            const float f  = __fdividef(576.0f, 576.0f + py);
            const float sb = fmaf(px, f, 287.0f);      // s - 0.5
            const float u  = sb + CMAGIC;              // RN -> round(s - 0.5)
            const int   i0 = __float_as_int(u) - CBITS;
            const float r  = u - CMAGIC;
            fr[j] = (sb - r) + 0.5f;                   // in [0, 1]
            const float2* __restrict__ row = &g_pad[(a + j) * PADW + POFF];
            v0[j] = __ldg(&row[i0]);
            v1[j] = __ldg(&row[i0 + 1]);
        }
        #pragma unroll
        for (int j = 0; j < 2; j++) {
            const float w0 = 1.0f - fr[j];
            accA = fmaf(v0[j].x, w0, accA);
            accA = fmaf(v1[j].x, fr[j], accA);
            accB = fmaf(v0[j].y, w0, accB);
            accB = fmaf(v1[j].y, fr[j], accB);
        }
    }
    const int p = y * W_IMG + x;
    g_img[p]    = accA;
    img_sino[p] = accB;
}

// ---------------------------------------------------------------------------
// Kernel 3: conv3 (2->1, 3x3, pad1), smem-tiled, 32x16 blocks.
// ---------------------------------------------------------------------------
#define DTX 32
#define DTY 16
__global__ void __launch_bounds__(DTX * DTY) conv3_kernel(
    const float* __restrict__ w3, const float* __restrict__ b3,
    const float* __restrict__ img_sino,
    float* __restrict__ img_pred)
{
    __shared__ float sI[DTY + 2][DTX + 2];
    __shared__ float sS[DTY + 2][DTX + 2];
    __shared__ float s_w[18];
    __shared__ float s_b;

    const int tid = threadIdx.y * DTX + threadIdx.x;
    if (tid < 18) s_w[tid] = w3[tid];
    if (tid == 18) s_b = b3[0];

    const int bx0 = blockIdx.x * DTX, by0 = blockIdx.y * DTY;
    for (int i = tid; i < (DTY + 2) * (DTX + 2); i += DTX * DTY) {
        int ly = i / (DTX + 2), lx = i % (DTX + 2);
        int gy = by0 - 1 + ly, gx = bx0 - 1 + lx;
        float vi = 0.0f, vs = 0.0f;
        if ((unsigned)gy < W_IMG && (unsigned)gx < W_IMG) {
            int q = gy * W_IMG + gx;
            vi = g_img[q];
            vs = __ldg(&img_sino[q]);
        }
        sI[ly][lx] = vi;
        sS[ly][lx] = vs;
    }
    __syncthreads();

    const int tx = threadIdx.x, ty = threadIdx.y;
    float acc = s_b;
    #pragma unroll
    for (int ky = 0; ky < 3; ky++)
        #pragma unroll
        for (int kx = 0; kx < 3; kx++) {
            acc = fmaf(sI[ty + ky][tx + kx], s_w[ky * 3 + kx],     acc);
            acc = fmaf(sS[ty + ky][tx + kx], s_w[9 + ky * 3 + kx], acc);
        }
    img_pred[(by0 + ty) * W_IMG + bx0 + tx] = acc;
}

// ---------------------------------------------------------------------------
extern "C" void kernel_launch(void* const* d_in, const int* in_sizes, int n_in,
                              void* d_out, int out_size)
{
    const float* sino   = (const float*)d_in[0];
    const float* angles = (const float*)d_in[1];
    const float* w1     = (const float*)d_in[2];
    const float* b1     = (const float*)d_in[3];
    const float* w2     = (const float*)d_in[4];
    const float* b2     = (const float*)d_in[5];
    const float* w3     = (const float*)d_in[6];
    const float* b3     = (const float*)d_in[7];

    float* out       = (float*)d_out;
    float* sino_pred = out;                               // 192*576 = 110592
    float* img_sino  = out + A_ANG * DDET;                // 384*384 = 147456
    float* img_pred  = out + A_ANG * DDET + W_IMG * W_IMG;

    dim3 grid1(DDET / CTX, A_ANG / CTY);
    dim3 block1(CTX, CTY);
    conv12_kernel<<<grid1, block1>>>(sino, w1, b1, w2, b2, sino_pred);

    border_fix_kernel<<<12, 256>>>(sino, w1, b1, w2, b2, sino_pred);

    dim3 grid2(W_IMG / 32, W_IMG / 32);
    backproj_kernel<<<grid2, 1024>>>(angles, img_sino);

    dim3 grid3(W_IMG / DTX, W_IMG / DTY);
    dim3 block3(DTX, DTY);
    conv3_kernel<<<grid3, block3>>>(w3, b3, img_sino, img_pred);
}

// round 12
// speedup vs baseline: 1.2872x; 1.2872x over previous
#include <cuda_runtime.h>

#define A_ANG 192
#define DDET  576
#define W_IMG 384
#define WW    (W_IMG * W_IMG)
#define PADW  672
#define POFF  24
#define CMAGIC 12582912.0f            /* 2^23 + 2^22 */
#define CBITS  0x4B400000             /* __float_as_int(CMAGIC) */

// Scratch (__device__ globals: allocation-free). g_pad is zero-initialized at
// module load; padding slots are never written, so they stay zero across all
// graph replays (out-of-range detector taps contribute exactly 0).
__device__ float2 g_pad[A_ANG * PADW];     // 1.0 MB packed (sino, pred) table
__device__ float  g_pA[2 * WW];            // partial backproj of raw sino (2 halves)
__device__ float  g_pB[2 * WW];            // partial backproj of sino_pred
__device__ float  g_G[625];                // G[d][e] = sum_c w2[c,d]*w1[c,e]
__device__ float  g_B[25];                 // B[d]    = sum_c w2[c,d]*b1[c]
__device__ float  g_W[81];                 // interior 9x9 composite kernel
__device__ float  g_bias[1];               // b2 + sum_d B[d]

// ---------------------------------------------------------------------------
// Kernel 0: build composite-conv tables (1 block, trivial cost)
// ---------------------------------------------------------------------------
__global__ void __launch_bounds__(640) precompute_kernel(
    const float* __restrict__ w1, const float* __restrict__ b1,
    const float* __restrict__ w2, const float* __restrict__ b2)
{
    __shared__ float sG[625];
    const int tid = threadIdx.x;
    if (tid < 625) {
        int d = tid / 25, e = tid % 25;
        float g = 0.0f;
        #pragma unroll
        for (int c = 0; c < 16; c++) g = fmaf(w2[c * 25 + d], w1[c * 25 + e], g);
        sG[tid] = g;
        g_G[tid] = g;
    }
    if (tid < 25) {
        float s = 0.0f;
        #pragma unroll
        for (int c = 0; c < 16; c++) s = fmaf(w2[c * 25 + tid], b1[c], s);
        g_B[tid] = s;
    }
    __syncthreads();
    if (tid < 81) {
        int tty = tid / 9, ttx = tid % 9;
        float w = 0.0f;
        for (int dy = 0; dy < 5; dy++) {
            int ey = tty - dy; if (ey < 0 || ey > 4) continue;
            for (int dx = 0; dx < 5; dx++) {
                int ex = ttx - dx; if (ex < 0 || ex > 4) continue;
                w += sG[(dy * 5 + dx) * 25 + ey * 5 + ex];
            }
        }
        g_W[tid] = w;
    }
    if (tid == 0) {
        float bias = b2[0];
        #pragma unroll
        for (int c = 0; c < 16; c++) {
            float s2 = 0.0f;
            #pragma unroll
            for (int d = 0; d < 25; d++) s2 += w2[c * 25 + d];
            bias = fmaf(s2, b1[c], bias);
        }
        g_bias[0] = bias;
    }
}

// ---------------------------------------------------------------------------
// Kernel 1: composite conv (sino -> sino_pred), writes packed padded sinogram.
// Interior pixels: 9x9 kernel W (81 FMA). Border pixels: exact per-d formula.
// (R9 config -- proven fastest front end.)
// ---------------------------------------------------------------------------
#define CTX 32
#define CTY 8
__global__ void __launch_bounds__(CTX * CTY) conv12_kernel(
    const float* __restrict__ sino,
    const float* __restrict__ b2,
    float* __restrict__ sino_pred)
{
    __shared__ float t[CTY + 8][CTX + 8];   // 16 x 40, halo 4, zero-padded
    __shared__ float sW[81];
    __shared__ float sG[625];
    __shared__ float sB[25];
    __shared__ float sbias;

    const int tid = threadIdx.y * CTX + threadIdx.x;
    if (tid < 81) sW[tid] = g_W[tid];
    for (int i = tid; i < 625; i += CTX * CTY) sG[i] = g_G[i];
    if (tid < 25) sB[tid] = g_B[tid];
    if (tid == 255) sbias = g_bias[0];

    const int bx0 = blockIdx.x * CTX, by0 = blockIdx.y * CTY;
    for (int i = tid; i < (CTY + 8) * (CTX + 8); i += CTX * CTY) {
        int ly = i / (CTX + 8), lx = i % (CTX + 8);
        int gy = by0 - 4 + ly, gx = bx0 - 4 + lx;
        float v = 0.0f;
        if ((unsigned)gy < A_ANG && (unsigned)gx < DDET) v = sino[gy * DDET + gx];
        t[ly][lx] = v;
    }
    __syncthreads();

    const int tx = threadIdx.x, ty = threadIdx.y;
    const int gx = bx0 + tx, gy = by0 + ty;
    float acc;
    const bool interior = (gy >= 2) && (gy <= A_ANG - 3) && (gx >= 2) && (gx <= DDET - 3);
    if (interior) {
        acc = sbias;
        #pragma unroll
        for (int a = 0; a < 9; a++)
            #pragma unroll
            for (int b = 0; b < 9; b++)
                acc = fmaf(t[ty + a][tx + b], sW[a * 9 + b], acc);
    } else {
        acc = b2[0];
        for (int dy = 0; dy < 5; dy++) {
            int hy = gy + dy - 2; if ((unsigned)hy >= A_ANG) continue;
            for (int dx = 0; dx < 5; dx++) {
                int hx = gx + dx - 2; if ((unsigned)hx >= DDET) continue;
                float a2 = sB[dy * 5 + dx];
                #pragma unroll
                for (int ey = 0; ey < 5; ey++)
                    #pragma unroll
                    for (int ex = 0; ex < 5; ex++)
                        a2 = fmaf(t[ty + dy + ey][tx + dx + ex],
                                  sG[(dy * 5 + dx) * 25 + ey * 5 + ex], a2);
                acc += a2;
            }
        }
    }
    const int idx = gy * DDET + gx;
    sino_pred[idx] = acc;
    g_pad[gy * PADW + POFF + gx] = make_float2(t[ty + 4][tx + 4], acc);
}

// ---------------------------------------------------------------------------
// Kernel 2: dual fan-beam backprojection, ANGLE-SPLIT x2.
// 32x32 tile / 1024 threads; grid (12,12,2) = 288 blocks -> 2 blocks/SM
// = 2048 threads/SM (~100% occ; regs <= 32). Each z handles 96 angles,
// writing partial planes. Floor via 2^23 trick (all fma/alu-pipe ops).
// ---------------------------------------------------------------------------
__global__ void __launch_bounds__(1024) backproj_kernel(
    const float* __restrict__ angles)
{
    __shared__ float2 s_ang[A_ANG / 2];
    const int tid = threadIdx.x;
    const int z = blockIdx.z;
    const int a0 = z * (A_ANG / 2);
    if (tid < A_ANG / 2) {
        float sv, cv;
        sincosf(angles[a0 + tid], &sv, &cv);
        s_ang[tid] = make_float2(cv, sv);
    }
    __syncthreads();

    // warp footprint 8x4; warps tiled 4 across x, 8 down y
    const int lane = tid & 31, wid = tid >> 5;
    const int lx = lane & 7,  ly = lane >> 3;      // 8 x 4
    const int wx = wid & 3,   wy = wid >> 2;       // 4 x 8
    const int x = blockIdx.x * 32 + wx * 8 + lx;
    const int y = blockIdx.y * 32 + wy * 4 + ly;
    const float X = (float)x - 191.5f;
    const float Y = (float)y - 191.5f;

    float accA = 0.f, accB = 0.f;
    for (int a = 0; a < A_ANG / 2; a += 2) {
        float2 v0[2], v1[2];
        float fr[2];
        #pragma unroll
        for (int j = 0; j < 2; j++) {
            const float2 cs = s_ang[a + j];
            const float px = fmaf(cs.x, X, cs.y * Y);
            const float py = fmaf(-cs.y, X, cs.x * Y);
            const float f  = __fdividef(576.0f, 576.0f + py);
            const float sb = fmaf(px, f, 287.0f);      // s - 0.5
            const float u  = sb + CMAGIC;              // RN -> round(s - 0.5)
            const int   i0 = __float_as_int(u) - CBITS;
            const float r  = u - CMAGIC;
            fr[j] = (sb - r) + 0.5f;                   // in [0, 1]
            const float2* __restrict__ row = &g_pad[(a0 + a + j) * PADW + POFF];
            v0[j] = __ldg(&row[i0]);
            v1[j] = __ldg(&row[i0 + 1]);
        }
        #pragma unroll
        for (int j = 0; j < 2; j++) {
            const float w0 = 1.0f - fr[j];
            accA = fmaf(v0[j].x, w0, accA);
            accA = fmaf(v1[j].x, fr[j], accA);
            accB = fmaf(v0[j].y, w0, accB);
            accB = fmaf(v1[j].y, fr[j], accB);
        }
    }
    const int p = y * W_IMG + x;
    g_pA[z * WW + p] = accA;
    g_pB[z * WW + p] = accB;
}

// ---------------------------------------------------------------------------
// Kernel 3: combine partials + conv3 (2->1, 3x3, pad1), smem-tiled.
// Stages img = pA0+pA1 and img_sino = pB0+pB1 in smem, writes BOTH the
// img_sino output and img_pred. 4 global loads per halo pixel.
// ---------------------------------------------------------------------------
#define DTX 32
#define DTY 16
__global__ void __launch_bounds__(DTX * DTY) conv3_kernel(
    const float* __restrict__ w3, const float* __restrict__ b3,
    float* __restrict__ img_sino,
    float* __restrict__ img_pred)
{
    __shared__ float sI[DTY + 2][DTX + 2];
    __shared__ float sS[DTY + 2][DTX + 2];
    __shared__ float s_w[18];
    __shared__ float s_b;

    const int tid = threadIdx.y * DTX + threadIdx.x;
    if (tid < 18) s_w[tid] = w3[tid];
    if (tid == 18) s_b = b3[0];

    const int bx0 = blockIdx.x * DTX, by0 = blockIdx.y * DTY;
    for (int i = tid; i < (DTY + 2) * (DTX + 2); i += DTX * DTY) {
        int ly = i / (DTX + 2), lx = i % (DTX + 2);
        int gy = by0 - 1 + ly, gx = bx0 - 1 + lx;
        float vi = 0.0f, vs = 0.0f;
        if ((unsigned)gy < W_IMG && (unsigned)gx < W_IMG) {
            int q = gy * W_IMG + gx;
            vi = g_pA[q] + g_pA[WW + q];
            vs = g_pB[q] + g_pB[WW + q];
        }
        sI[ly][lx] = vi;
        sS[ly][lx] = vs;
    }
    __syncthreads();

    const int tx = threadIdx.x, ty = threadIdx.y;
    float acc = s_b;
    #pragma unroll
    for (int ky = 0; ky < 3; ky++)
        #pragma unroll
        for (int kx = 0; kx < 3; kx++) {
            acc = fmaf(sI[ty + ky][tx + kx], s_w[ky * 3 + kx],     acc);
            acc = fmaf(sS[ty + ky][tx + kx], s_w[9 + ky * 3 + kx], acc);
        }
    const int p = (by0 + ty) * W_IMG + bx0 + tx;
    img_sino[p] = sS[ty + 1][tx + 1];
    img_pred[p] = acc;
}

// ---------------------------------------------------------------------------
extern "C" void kernel_launch(void* const* d_in, const int* in_sizes, int n_in,
                              void* d_out, int out_size)
{
    const float* sino   = (const float*)d_in[0];
    const float* angles = (const float*)d_in[1];
    const float* w1     = (const float*)d_in[2];
    const float* b1     = (const float*)d_in[3];
    const float* w2     = (const float*)d_in[4];
    const float* b2     = (const float*)d_in[5];
    const float* w3     = (const float*)d_in[6];
    const float* b3     = (const float*)d_in[7];

    float* out       = (float*)d_out;
    float* sino_pred = out;                               // 192*576 = 110592
    float* img_sino  = out + A_ANG * DDET;                // 384*384 = 147456
    float* img_pred  = out + A_ANG * DDET + WW;

    precompute_kernel<<<1, 640>>>(w1, b1, w2, b2);

    dim3 grid1(DDET / CTX, A_ANG / CTY);
    dim3 block1(CTX, CTY);
    conv12_kernel<<<grid1, block1>>>(sino, b2, sino_pred);

    dim3 grid2(W_IMG / 32, W_IMG / 32, 2);
    backproj_kernel<<<grid2, 1024>>>(angles);

    dim3 grid3(W_IMG / DTX, W_IMG / DTY);
    dim3 block3(DTX, DTY);
    conv3_kernel<<<grid3, block3>>>(w3, b3, img_sino, img_pred);
}